// round 1
// baseline (speedup 1.0000x reference)
#include <cuda_runtime.h>
#include <math.h>

#define TPB 256
#define KC 10     // n_point_candidate
#define NKP 9     // 8 keypoints + 1 center

__global__ __launch_bounds__(TPB)
void pose_kernel(const float* __restrict__ pcld,
                 const float* __restrict__ kpts,
                 const float* __restrict__ cpt,
                 const float* __restrict__ seg,
                 const float* __restrict__ mesh,
                 float* __restrict__ outR,
                 float* __restrict__ outT,
                 float* __restrict__ outV,
                 int n)
{
    const int b   = blockIdx.x;
    const int tid = threadIdx.x;

    __shared__ float sv[TPB * KC];
    __shared__ int   si[TPB * KC];
    __shared__ float cand[NKP][KC][3];
    __shared__ float voted[NKP][3];

    // ---------------- per-thread register top-10 ----------------
    float lv[KC]; int li[KC];
#pragma unroll
    for (int i = 0; i < KC; i++) { lv[i] = -INFINITY; li[i] = -1; }
    float lmin = -INFINITY;

    const float*  segb = seg + (long long)b * n;
    const int     n4   = n >> 2;
    const float4* seg4 = (const float4*)segb;

    for (int i4 = tid; i4 < n4; i4 += TPB) {
        float4 v = seg4[i4];
        float xs[4] = {v.x, v.y, v.z, v.w};
#pragma unroll
        for (int c = 0; c < 4; c++) {
            float x = xs[c];
            if (x > lmin) {
                int id = (i4 << 2) + c;
                float vx = x; int vi = id;
#pragma unroll
                for (int p = 0; p < KC; p++) {
                    if (vx > lv[p]) {
                        float tv = lv[p]; lv[p] = vx; vx = tv;
                        int   ti = li[p]; li[p] = vi; vi = ti;
                    }
                }
                lmin = lv[KC - 1];
            }
        }
    }
    // scalar tail (n not multiple of 4)
    for (int i = (n4 << 2) + tid; i < n; i += TPB) {
        float x = segb[i];
        if (x > lmin) {
            float vx = x; int vi = i;
#pragma unroll
            for (int p = 0; p < KC; p++) {
                if (vx > lv[p]) {
                    float tv = lv[p]; lv[p] = vx; vx = tv;
                    int   ti = li[p]; li[p] = vi; vi = ti;
                }
            }
            lmin = lv[KC - 1];
        }
    }

#pragma unroll
    for (int i = 0; i < KC; i++) { sv[tid * KC + i] = lv[i]; si[tid * KC + i] = li[i]; }

    // ---------------- tree merge of sorted descending lists ----------------
#pragma unroll 1
    for (int stride = 1; stride < TPB; stride <<= 1) {
        __syncthreads();
        if ((tid & (2 * stride - 1)) == 0) {
            const float* pa = &sv[tid * KC];             const int* ia = &si[tid * KC];
            const float* pb = &sv[(tid + stride) * KC];  const int* ib = &si[(tid + stride) * KC];
            float mv[KC]; int mi[KC];
            int a = 0, bb = 0;
#pragma unroll
            for (int k = 0; k < KC; k++) {
                float va = pa[a], vb = pb[bb];
                if (va >= vb) { mv[k] = va; mi[k] = ia[a]; a++; }
                else          { mv[k] = vb; mi[k] = ib[bb]; bb++; }
            }
#pragma unroll
            for (int k = 0; k < KC; k++) { sv[tid * KC + k] = mv[k]; si[tid * KC + k] = mi[k]; }
        }
    }
    __syncthreads();

    // ---------------- build candidates (90 threads) ----------------
    if (tid < NKP * KC) {
        int i  = tid / KC;           // keypoint
        int j  = tid % KC;           // candidate
        int id = si[j];
        const float* p = pcld + ((long long)b * n + id) * 3;
        const float* o = (i < 8)
            ? (kpts + (((long long)b * n + id) * 8 + i) * 3)
            : (cpt  + ((long long)b * n + id) * 3);
        cand[i][j][0] = p[0] + o[0];
        cand[i][j][1] = p[1] + o[1];
        cand[i][j][2] = p[2] + o[2];
    }
    __syncthreads();

    // ---------------- clustering with std filter (9 threads) ----------------
    if (tid < NKP) {
        float m0 = 0.f, m1 = 0.f, m2 = 0.f;
#pragma unroll
        for (int j = 0; j < KC; j++) { m0 += cand[tid][j][0]; m1 += cand[tid][j][1]; m2 += cand[tid][j][2]; }
        m0 *= 0.1f; m1 *= 0.1f; m2 *= 0.1f;
        float v0 = 0.f, v1 = 0.f, v2 = 0.f;
#pragma unroll
        for (int j = 0; j < KC; j++) {
            float d0 = cand[tid][j][0] - m0, d1 = cand[tid][j][1] - m1, d2 = cand[tid][j][2] - m2;
            v0 += d0 * d0; v1 += d1 * d1; v2 += d2 * d2;
        }
        float s0 = sqrtf(v0 * 0.1f), s1 = sqrtf(v1 * 0.1f), s2 = sqrtf(v2 * 0.1f);
        float a0 = 0.f, a1 = 0.f, a2 = 0.f, cnt = 0.f;
#pragma unroll
        for (int j = 0; j < KC; j++) {
            float c0 = cand[tid][j][0], c1 = cand[tid][j][1], c2 = cand[tid][j][2];
            bool in = (fabsf(c0 - m0) <= s0) && (fabsf(c1 - m1) <= s1) && (fabsf(c2 - m2) <= s2);
            if (in) { cnt += 1.f; a0 += c0; a1 += c1; a2 += c2; }
        }
        float inv = 1.0f / (cnt + 1e-6f);
        float w0 = a0 * inv, w1 = a1 * inv, w2 = a2 * inv;
        voted[tid][0] = w0; voted[tid][1] = w1; voted[tid][2] = w2;
        long long vo = ((long long)b * NKP + tid) * 3;
        outV[vo + 0] = w0; outV[vo + 1] = w1; outV[vo + 2] = w2;
    }
    __syncthreads();

    // ---------------- Kabsch + 3x3 SVD (thread 0, fp64) ----------------
    if (tid == 0) {
        const float* mb = mesh + (long long)b * NKP * 3;
        double cA[3] = {0, 0, 0}, cB[3] = {0, 0, 0};
        for (int i = 0; i < NKP; i++) {
            cA[0] += mb[i * 3 + 0]; cA[1] += mb[i * 3 + 1]; cA[2] += mb[i * 3 + 2];
            cB[0] += voted[i][0];   cB[1] += voted[i][1];   cB[2] += voted[i][2];
        }
        const double inv9 = 1.0 / 9.0;
        cA[0] *= inv9; cA[1] *= inv9; cA[2] *= inv9;
        cB[0] *= inv9; cB[1] *= inv9; cB[2] *= inv9;

        double H[3][3] = {{0,0,0},{0,0,0},{0,0,0}};
        for (int i = 0; i < NKP; i++) {
            double am[3] = {mb[i*3+0] - cA[0], mb[i*3+1] - cA[1], mb[i*3+2] - cA[2]};
            double bm[3] = {voted[i][0] - cB[0], voted[i][1] - cB[1], voted[i][2] - cB[2]};
            for (int r = 0; r < 3; r++)
                for (int c = 0; c < 3; c++)
                    H[r][c] += am[r] * bm[c];
        }

        // K = H^T H (symmetric)
        double K[3][3];
        for (int r = 0; r < 3; r++)
            for (int c = 0; c < 3; c++)
                K[r][c] = H[0][r]*H[0][c] + H[1][r]*H[1][c] + H[2][r]*H[2][c];

        double V[3][3] = {{1,0,0},{0,1,0},{0,0,1}};
        const double tr2 = (K[0][0] + K[1][1] + K[2][2]);
        const double tol = 1e-24 * tr2 * tr2 + 1e-300;

        const int PP[3] = {0, 0, 1};
        const int QQ[3] = {1, 2, 2};
        for (int sweep = 0; sweep < 12; sweep++) {
            double off = K[0][1]*K[0][1] + K[0][2]*K[0][2] + K[1][2]*K[1][2];
            if (off < tol) break;
            for (int pr = 0; pr < 3; pr++) {
                int p = PP[pr], q = QQ[pr];
                double apq = K[p][q];
                if (apq == 0.0) continue;
                double theta = (K[q][q] - K[p][p]) / (2.0 * apq);
                double t = ((theta >= 0.0) ? 1.0 : -1.0) / (fabs(theta) + sqrt(theta*theta + 1.0));
                double cc = 1.0 / sqrt(t*t + 1.0);
                double ss = t * cc;
                K[p][p] -= t * apq;
                K[q][q] += t * apq;
                K[p][q] = 0.0; K[q][p] = 0.0;
                int r3 = 3 - p - q;
                double krp = K[r3][p], krq = K[r3][q];
                K[r3][p] = cc*krp - ss*krq;  K[p][r3] = K[r3][p];
                K[r3][q] = ss*krp + cc*krq;  K[q][r3] = K[r3][q];
                for (int k = 0; k < 3; k++) {
                    double vp = V[k][p], vq = V[k][q];
                    V[k][p] = cc*vp - ss*vq;
                    V[k][q] = ss*vp + cc*vq;
                }
            }
        }

        // sort eigenvalues descending
        int ord[3] = {0, 1, 2};
        for (int i = 0; i < 2; i++)
            for (int j = i + 1; j < 3; j++)
                if (K[ord[j]][ord[j]] > K[ord[i]][ord[i]]) { int t2 = ord[i]; ord[i] = ord[j]; ord[j] = t2; }

        double v1[3], v2[3], v3[3];
        for (int c = 0; c < 3; c++) { v1[c] = V[c][ord[0]]; v2[c] = V[c][ord[1]]; v3[c] = V[c][ord[2]]; }

        double u1[3], u2[3], u3[3];
        for (int r = 0; r < 3; r++) u1[r] = H[r][0]*v1[0] + H[r][1]*v1[1] + H[r][2]*v1[2];
        double n1 = sqrt(u1[0]*u1[0] + u1[1]*u1[1] + u1[2]*u1[2]);
        double in1 = (n1 > 1e-30) ? 1.0 / n1 : 0.0;
        u1[0] *= in1; u1[1] *= in1; u1[2] *= in1;

        for (int r = 0; r < 3; r++) u2[r] = H[r][0]*v2[0] + H[r][1]*v2[1] + H[r][2]*v2[2];
        double d12 = u2[0]*u1[0] + u2[1]*u1[1] + u2[2]*u1[2];
        u2[0] -= d12 * u1[0]; u2[1] -= d12 * u1[1]; u2[2] -= d12 * u1[2];
        double n2 = sqrt(u2[0]*u2[0] + u2[1]*u2[1] + u2[2]*u2[2]);
        double in2 = (n2 > 1e-30) ? 1.0 / n2 : 0.0;
        u2[0] *= in2; u2[1] *= in2; u2[2] *= in2;

        u3[0] = u1[1]*u2[2] - u1[2]*u2[1];
        u3[1] = u1[2]*u2[0] - u1[0]*u2[2];
        u3[2] = u1[0]*u2[1] - u1[1]*u2[0];

        double R[3][3];
        for (int r = 0; r < 3; r++)
            for (int c = 0; c < 3; c++)
                R[r][c] = v1[r]*u1[c] + v2[r]*u2[c] + v3[r]*u3[c];

        double det = R[0][0]*(R[1][1]*R[2][2] - R[1][2]*R[2][1])
                   - R[0][1]*(R[1][0]*R[2][2] - R[1][2]*R[2][0])
                   + R[0][2]*(R[1][0]*R[2][1] - R[1][1]*R[2][0]);
        if (det < 0.0) {
            for (int r = 0; r < 3; r++)
                for (int c = 0; c < 3; c++)
                    R[r][c] -= 2.0 * v3[r] * u3[c];
        }

        long long ro = (long long)b * 9;
        for (int r = 0; r < 3; r++)
            for (int c = 0; c < 3; c++)
                outR[ro + r*3 + c] = (float)R[r][c];

        long long to = (long long)b * 3;
        for (int c = 0; c < 3; c++) {
            double tc = cB[c] - (R[c][0]*cA[0] + R[c][1]*cA[1] + R[c][2]*cA[2]);
            outT[to + c] = (float)tc;
        }
    }
}

extern "C" void kernel_launch(void* const* d_in, const int* in_sizes, int n_in,
                              void* d_out, int out_size)
{
    const float* pcld = (const float*)d_in[0];  // [b,n,3]
    const float* kpts = (const float*)d_in[1];  // [b,n,8,3]
    const float* cpt  = (const float*)d_in[2];  // [b,n,1,3]
    const float* seg  = (const float*)d_in[3];  // [b,n,1]
    const float* mesh = (const float*)d_in[4];  // [b,9,3]

    int b = in_sizes[4] / 27;       // mesh is b*9*3
    int n = in_sizes[3] / b;        // seg is b*n

    float* out  = (float*)d_out;
    float* outR = out;              // b*9
    float* outT = out + (long long)b * 9;   // b*3
    float* outV = out + (long long)b * 12;  // b*27

    pose_kernel<<<b, TPB>>>(pcld, kpts, cpt, seg, mesh, outR, outT, outV, n);
}

// round 2
// speedup vs baseline: 1.2305x; 1.2305x over previous
#include <cuda_runtime.h>
#include <math.h>

#define TPB   256
#define KC    10      // n_point_candidate
#define NKP   9       // 8 keypoints + 1 center
#define SPLIT 16      // scan blocks per batch
#define MAXB  64

// partial top-10 lists per (batch, split)
__device__ float g_pv[MAXB * SPLIT * KC];
__device__ int   g_pi[MAXB * SPLIT * KC];

// ---------------------------------------------------------------------------
// Kernel A: partial top-10 scan.  grid = (b, SPLIT), block = TPB
// ---------------------------------------------------------------------------
__global__ __launch_bounds__(TPB)
void topk_partial_kernel(const float* __restrict__ seg, int n)
{
    const int b   = blockIdx.x;
    const int s   = blockIdx.y;
    const int tid = threadIdx.x;

    const int chunk = (n + SPLIT - 1) / SPLIT;
    const int begin = s * chunk;
    const int end   = min(n, begin + chunk);

    __shared__ float sv[TPB * KC];
    __shared__ int   si[TPB * KC];

    float lv[KC]; int li[KC];
#pragma unroll
    for (int i = 0; i < KC; i++) { lv[i] = -INFINITY; li[i] = -1; }
    float lmin = -INFINITY;

    const float* segb = seg + (long long)b * n;
    // each thread touches ~chunk/TPB (=3) strided elements; loads are
    // independent -> MLP = iterations
    for (int i = begin + tid; i < end; i += TPB) {
        float x = segb[i];
        if (x > lmin) {
            float vx = x; int vi = i;
#pragma unroll
            for (int p = 0; p < KC; p++) {
                if (vx > lv[p]) {
                    float tv = lv[p]; lv[p] = vx; vx = tv;
                    int   ti = li[p]; li[p] = vi; vi = ti;
                }
            }
            lmin = lv[KC - 1];
        }
    }

#pragma unroll
    for (int i = 0; i < KC; i++) { sv[tid * KC + i] = lv[i]; si[tid * KC + i] = li[i]; }

    // tree merge of sorted descending lists
#pragma unroll 1
    for (int stride = 1; stride < TPB; stride <<= 1) {
        __syncthreads();
        if ((tid & (2 * stride - 1)) == 0) {
            const float* pa = &sv[tid * KC];             const int* ia = &si[tid * KC];
            const float* pb = &sv[(tid + stride) * KC];  const int* ib = &si[(tid + stride) * KC];
            float mv[KC]; int mi[KC];
            int a = 0, bb = 0;
#pragma unroll
            for (int k = 0; k < KC; k++) {
                float va = pa[a], vb = pb[bb];
                if (va >= vb) { mv[k] = va; mi[k] = ia[a]; a++; }
                else          { mv[k] = vb; mi[k] = ib[bb]; bb++; }
            }
#pragma unroll
            for (int k = 0; k < KC; k++) { sv[tid * KC + k] = mv[k]; si[tid * KC + k] = mi[k]; }
        }
    }
    __syncthreads();

    if (tid < KC) {
        int o = (b * SPLIT + s) * KC + tid;
        g_pv[o] = sv[tid];
        g_pi[o] = si[tid];
    }
}

// ---------------------------------------------------------------------------
// Kernel B: merge partials + candidates + clustering + Kabsch (fp32 SVD).
// grid = b, block = TPB
// ---------------------------------------------------------------------------
__global__ __launch_bounds__(TPB)
void pose_finalize_kernel(const float* __restrict__ pcld,
                          const float* __restrict__ kpts,
                          const float* __restrict__ cpt,
                          const float* __restrict__ mesh,
                          float* __restrict__ outR,
                          float* __restrict__ outT,
                          float* __restrict__ outV,
                          int n)
{
    const int b   = blockIdx.x;
    const int tid = threadIdx.x;
    const int NC  = SPLIT * KC;   // 160 merged candidates

    __shared__ float mv[NC];
    __shared__ int   mi[NC];
    __shared__ int   topi[KC];
    __shared__ float cand[NKP][KC][3];
    __shared__ float voted[NKP][3];

    if (tid < NC) {
        mv[tid] = g_pv[b * NC + tid];
        mi[tid] = g_pi[b * NC + tid];
    }
    __syncthreads();

    // rank by counting (value desc, index asc tie-break)
    if (tid < NC) {
        float v = mv[tid]; int id = mi[tid];
        int rank = 0;
#pragma unroll 8
        for (int j = 0; j < NC; j++) {
            float vj = mv[j]; int ij = mi[j];
            rank += (vj > v) || (vj == v && ij < id);
        }
        if (rank < KC) topi[rank] = id;
    }
    __syncthreads();

    // build candidates (90 threads; scattered gathers, independent -> MLP)
    if (tid < NKP * KC) {
        int i  = tid / KC;           // keypoint
        int j  = tid % KC;           // candidate
        int id = topi[j];
        const float* p = pcld + ((long long)b * n + id) * 3;
        const float* o = (i < 8)
            ? (kpts + (((long long)b * n + id) * 8 + i) * 3)
            : (cpt  + ((long long)b * n + id) * 3);
        cand[i][j][0] = p[0] + o[0];
        cand[i][j][1] = p[1] + o[1];
        cand[i][j][2] = p[2] + o[2];
    }
    __syncthreads();

    // clustering with std filter (9 threads)
    if (tid < NKP) {
        float m0 = 0.f, m1 = 0.f, m2 = 0.f;
#pragma unroll
        for (int j = 0; j < KC; j++) { m0 += cand[tid][j][0]; m1 += cand[tid][j][1]; m2 += cand[tid][j][2]; }
        m0 *= 0.1f; m1 *= 0.1f; m2 *= 0.1f;
        float v0 = 0.f, v1 = 0.f, v2 = 0.f;
#pragma unroll
        for (int j = 0; j < KC; j++) {
            float d0 = cand[tid][j][0] - m0, d1 = cand[tid][j][1] - m1, d2 = cand[tid][j][2] - m2;
            v0 += d0 * d0; v1 += d1 * d1; v2 += d2 * d2;
        }
        float s0 = sqrtf(v0 * 0.1f), s1 = sqrtf(v1 * 0.1f), s2 = sqrtf(v2 * 0.1f);
        float a0 = 0.f, a1 = 0.f, a2 = 0.f, cnt = 0.f;
#pragma unroll
        for (int j = 0; j < KC; j++) {
            float c0 = cand[tid][j][0], c1 = cand[tid][j][1], c2 = cand[tid][j][2];
            bool in = (fabsf(c0 - m0) <= s0) && (fabsf(c1 - m1) <= s1) && (fabsf(c2 - m2) <= s2);
            if (in) { cnt += 1.f; a0 += c0; a1 += c1; a2 += c2; }
        }
        float inv = 1.0f / (cnt + 1e-6f);
        float w0 = a0 * inv, w1 = a1 * inv, w2 = a2 * inv;
        voted[tid][0] = w0; voted[tid][1] = w1; voted[tid][2] = w2;
        long long vo = ((long long)b * NKP + tid) * 3;
        outV[vo + 0] = w0; outV[vo + 1] = w1; outV[vo + 2] = w2;
    }
    __syncthreads();

    // Kabsch + 3x3 SVD (thread 0, fp32)
    if (tid == 0) {
        const float* mb = mesh + (long long)b * NKP * 3;
        float cA[3] = {0, 0, 0}, cB[3] = {0, 0, 0};
#pragma unroll
        for (int i = 0; i < NKP; i++) {
            cA[0] += mb[i * 3 + 0]; cA[1] += mb[i * 3 + 1]; cA[2] += mb[i * 3 + 2];
            cB[0] += voted[i][0];   cB[1] += voted[i][1];   cB[2] += voted[i][2];
        }
        const float inv9 = 1.0f / 9.0f;
        cA[0] *= inv9; cA[1] *= inv9; cA[2] *= inv9;
        cB[0] *= inv9; cB[1] *= inv9; cB[2] *= inv9;

        float H[3][3] = {{0,0,0},{0,0,0},{0,0,0}};
#pragma unroll
        for (int i = 0; i < NKP; i++) {
            float am[3] = {mb[i*3+0] - cA[0], mb[i*3+1] - cA[1], mb[i*3+2] - cA[2]};
            float bm[3] = {voted[i][0] - cB[0], voted[i][1] - cB[1], voted[i][2] - cB[2]};
#pragma unroll
            for (int r = 0; r < 3; r++)
#pragma unroll
                for (int c = 0; c < 3; c++)
                    H[r][c] += am[r] * bm[c];
        }

        // K = H^T H (symmetric)
        float K[3][3];
#pragma unroll
        for (int r = 0; r < 3; r++)
#pragma unroll
            for (int c = 0; c < 3; c++)
                K[r][c] = H[0][r]*H[0][c] + H[1][r]*H[1][c] + H[2][r]*H[2][c];

        float V[3][3] = {{1,0,0},{0,1,0},{0,0,1}};
        const float tr2 = (K[0][0] + K[1][1] + K[2][2]);
        const float tol = 1e-14f * tr2 * tr2 + 1e-30f;

        const int PP[3] = {0, 0, 1};
        const int QQ[3] = {1, 2, 2};
#pragma unroll 1
        for (int sweep = 0; sweep < 8; sweep++) {
            float off = K[0][1]*K[0][1] + K[0][2]*K[0][2] + K[1][2]*K[1][2];
            if (off < tol) break;
#pragma unroll
            for (int pr = 0; pr < 3; pr++) {
                int p = PP[pr], q = QQ[pr];
                float apq = K[p][q];
                if (apq == 0.0f) continue;
                float theta = (K[q][q] - K[p][p]) / (2.0f * apq);
                float t = ((theta >= 0.0f) ? 1.0f : -1.0f) / (fabsf(theta) + sqrtf(theta*theta + 1.0f));
                float cc = rsqrtf(t*t + 1.0f);
                float ss = t * cc;
                K[p][p] -= t * apq;
                K[q][q] += t * apq;
                K[p][q] = 0.0f; K[q][p] = 0.0f;
                int r3 = 3 - p - q;
                float krp = K[r3][p], krq = K[r3][q];
                K[r3][p] = cc*krp - ss*krq;  K[p][r3] = K[r3][p];
                K[r3][q] = ss*krp + cc*krq;  K[q][r3] = K[r3][q];
#pragma unroll
                for (int k = 0; k < 3; k++) {
                    float vp = V[k][p], vq = V[k][q];
                    V[k][p] = cc*vp - ss*vq;
                    V[k][q] = ss*vp + cc*vq;
                }
            }
        }

        // sort eigenvalues descending
        int ord[3] = {0, 1, 2};
#pragma unroll
        for (int i = 0; i < 2; i++)
#pragma unroll
            for (int j = i + 1; j < 3; j++)
                if (K[ord[j]][ord[j]] > K[ord[i]][ord[i]]) { int t2 = ord[i]; ord[i] = ord[j]; ord[j] = t2; }

        float v1[3], v2[3], v3[3];
#pragma unroll
        for (int c = 0; c < 3; c++) { v1[c] = V[c][ord[0]]; v2[c] = V[c][ord[1]]; v3[c] = V[c][ord[2]]; }

        float u1[3], u2[3], u3[3];
#pragma unroll
        for (int r = 0; r < 3; r++) u1[r] = H[r][0]*v1[0] + H[r][1]*v1[1] + H[r][2]*v1[2];
        float n1 = sqrtf(u1[0]*u1[0] + u1[1]*u1[1] + u1[2]*u1[2]);
        float in1 = (n1 > 1e-20f) ? 1.0f / n1 : 0.0f;
        u1[0] *= in1; u1[1] *= in1; u1[2] *= in1;

#pragma unroll
        for (int r = 0; r < 3; r++) u2[r] = H[r][0]*v2[0] + H[r][1]*v2[1] + H[r][2]*v2[2];
        float d12 = u2[0]*u1[0] + u2[1]*u1[1] + u2[2]*u1[2];
        u2[0] -= d12 * u1[0]; u2[1] -= d12 * u1[1]; u2[2] -= d12 * u1[2];
        float n2 = sqrtf(u2[0]*u2[0] + u2[1]*u2[1] + u2[2]*u2[2]);
        float in2 = (n2 > 1e-20f) ? 1.0f / n2 : 0.0f;
        u2[0] *= in2; u2[1] *= in2; u2[2] *= in2;

        u3[0] = u1[1]*u2[2] - u1[2]*u2[1];
        u3[1] = u1[2]*u2[0] - u1[0]*u2[2];
        u3[2] = u1[0]*u2[1] - u1[1]*u2[0];

        float R[3][3];
#pragma unroll
        for (int r = 0; r < 3; r++)
#pragma unroll
            for (int c = 0; c < 3; c++)
                R[r][c] = v1[r]*u1[c] + v2[r]*u2[c] + v3[r]*u3[c];

        float det = R[0][0]*(R[1][1]*R[2][2] - R[1][2]*R[2][1])
                  - R[0][1]*(R[1][0]*R[2][2] - R[1][2]*R[2][0])
                  + R[0][2]*(R[1][0]*R[2][1] - R[1][1]*R[2][0]);
        if (det < 0.0f) {
#pragma unroll
            for (int r = 0; r < 3; r++)
#pragma unroll
                for (int c = 0; c < 3; c++)
                    R[r][c] -= 2.0f * v3[r] * u3[c];
        }

        long long ro = (long long)b * 9;
#pragma unroll
        for (int r = 0; r < 3; r++)
#pragma unroll
            for (int c = 0; c < 3; c++)
                outR[ro + r*3 + c] = R[r][c];

        long long to = (long long)b * 3;
#pragma unroll
        for (int c = 0; c < 3; c++) {
            float tc = cB[c] - (R[c][0]*cA[0] + R[c][1]*cA[1] + R[c][2]*cA[2]);
            outT[to + c] = tc;
        }
    }
}

extern "C" void kernel_launch(void* const* d_in, const int* in_sizes, int n_in,
                              void* d_out, int out_size)
{
    const float* pcld = (const float*)d_in[0];  // [b,n,3]
    const float* kpts = (const float*)d_in[1];  // [b,n,8,3]
    const float* cpt  = (const float*)d_in[2];  // [b,n,1,3]
    const float* seg  = (const float*)d_in[3];  // [b,n,1]
    const float* mesh = (const float*)d_in[4];  // [b,9,3]

    int b = in_sizes[4] / 27;       // mesh is b*9*3
    int n = in_sizes[3] / b;        // seg is b*n

    float* out  = (float*)d_out;
    float* outR = out;                      // b*9
    float* outT = out + (long long)b * 9;   // b*3
    float* outV = out + (long long)b * 12;  // b*27

    dim3 gridA(b, SPLIT);
    topk_partial_kernel<<<gridA, TPB>>>(seg, n);
    pose_finalize_kernel<<<b, TPB>>>(pcld, kpts, cpt, mesh, outR, outT, outV, n);
}

// round 3
// speedup vs baseline: 2.4692x; 2.0067x over previous
#include <cuda_runtime.h>
#include <math.h>

#define TPB  256
#define KC   10      // n_point_candidate
#define NKP  9       // 8 keypoints + 1 center
#define MLPB 6       // float4 loads batched per iteration (MLP)

__global__ __launch_bounds__(TPB)
void pose_fused_kernel(const float* __restrict__ pcld,
                       const float* __restrict__ kpts,
                       const float* __restrict__ cpt,
                       const float* __restrict__ seg,
                       const float* __restrict__ mesh,
                       float* __restrict__ outR,
                       float* __restrict__ outT,
                       float* __restrict__ outV,
                       int n)
{
    const int b   = blockIdx.x;
    const int tid = threadIdx.x;

    __shared__ float sv[TPB * KC];
    __shared__ int   si[TPB * KC];
    __shared__ float cand[NKP][KC][3];
    __shared__ float voted[NKP][3];

    // ---------------- per-thread register top-10, batched loads ----------------
    float lv[KC]; int li[KC];
#pragma unroll
    for (int i = 0; i < KC; i++) { lv[i] = -INFINITY; li[i] = -1; }
    float lmin = -INFINITY;

    const float*  segb = seg + (long long)b * n;
    const int     nf4  = n >> 2;
    const float4* seg4 = (const float4*)segb;

    for (int base = tid; base < nf4; base += TPB * MLPB) {
        // issue all MLPB loads before any data-dependent work -> MLP = MLPB
        float4 buf[MLPB];
#pragma unroll
        for (int j = 0; j < MLPB; j++) {
            int i4 = base + j * TPB;
            buf[j] = (i4 < nf4) ? seg4[i4]
                                : make_float4(-INFINITY, -INFINITY, -INFINITY, -INFINITY);
        }
#pragma unroll
        for (int j = 0; j < MLPB; j++) {
            int i4 = base + j * TPB;
            float xs[4] = {buf[j].x, buf[j].y, buf[j].z, buf[j].w};
#pragma unroll
            for (int c = 0; c < 4; c++) {
                float x = xs[c];
                if (x > lmin) {
                    float vx = x; int vi = (i4 << 2) + c;
#pragma unroll
                    for (int p = 0; p < KC; p++) {
                        if (vx > lv[p]) {
                            float tv = lv[p]; lv[p] = vx; vx = tv;
                            int   ti = li[p]; li[p] = vi; vi = ti;
                        }
                    }
                    lmin = lv[KC - 1];
                }
            }
        }
    }
    // scalar tail (n % 4)
    for (int i = (nf4 << 2) + tid; i < n; i += TPB) {
        float x = segb[i];
        if (x > lmin) {
            float vx = x; int vi = i;
#pragma unroll
            for (int p = 0; p < KC; p++) {
                if (vx > lv[p]) {
                    float tv = lv[p]; lv[p] = vx; vx = tv;
                    int   ti = li[p]; li[p] = vi; vi = ti;
                }
            }
            lmin = lv[KC - 1];
        }
    }

#pragma unroll
    for (int i = 0; i < KC; i++) { sv[tid * KC + i] = lv[i]; si[tid * KC + i] = li[i]; }

    // ---------------- tree merge of sorted descending lists ----------------
#pragma unroll 1
    for (int stride = 1; stride < TPB; stride <<= 1) {
        __syncthreads();
        if ((tid & (2 * stride - 1)) == 0) {
            const float* pa = &sv[tid * KC];             const int* ia = &si[tid * KC];
            const float* pb = &sv[(tid + stride) * KC];  const int* ib = &si[(tid + stride) * KC];
            float mv[KC]; int mi[KC];
            int a = 0, bb = 0;
#pragma unroll
            for (int k = 0; k < KC; k++) {
                float va = pa[a], vb = pb[bb];
                if (va >= vb) { mv[k] = va; mi[k] = ia[a]; a++; }
                else          { mv[k] = vb; mi[k] = ib[bb]; bb++; }
            }
#pragma unroll
            for (int k = 0; k < KC; k++) { sv[tid * KC + k] = mv[k]; si[tid * KC + k] = mi[k]; }
        }
    }
    __syncthreads();

    // ---------------- build candidates (90 threads) ----------------
    if (tid < NKP * KC) {
        int i  = tid / KC;           // keypoint
        int j  = tid % KC;           // candidate
        int id = si[j];
        const float* p = pcld + ((long long)b * n + id) * 3;
        const float* o = (i < 8)
            ? (kpts + (((long long)b * n + id) * 8 + i) * 3)
            : (cpt  + ((long long)b * n + id) * 3);
        cand[i][j][0] = p[0] + o[0];
        cand[i][j][1] = p[1] + o[1];
        cand[i][j][2] = p[2] + o[2];
    }
    __syncthreads();

    // ---------------- clustering with std filter (9 threads) ----------------
    if (tid < NKP) {
        float m0 = 0.f, m1 = 0.f, m2 = 0.f;
#pragma unroll
        for (int j = 0; j < KC; j++) { m0 += cand[tid][j][0]; m1 += cand[tid][j][1]; m2 += cand[tid][j][2]; }
        m0 *= 0.1f; m1 *= 0.1f; m2 *= 0.1f;
        float v0 = 0.f, v1 = 0.f, v2 = 0.f;
#pragma unroll
        for (int j = 0; j < KC; j++) {
            float d0 = cand[tid][j][0] - m0, d1 = cand[tid][j][1] - m1, d2 = cand[tid][j][2] - m2;
            v0 += d0 * d0; v1 += d1 * d1; v2 += d2 * d2;
        }
        float s0 = sqrtf(v0 * 0.1f), s1 = sqrtf(v1 * 0.1f), s2 = sqrtf(v2 * 0.1f);
        float a0 = 0.f, a1 = 0.f, a2 = 0.f, cnt = 0.f;
#pragma unroll
        for (int j = 0; j < KC; j++) {
            float c0 = cand[tid][j][0], c1 = cand[tid][j][1], c2 = cand[tid][j][2];
            bool in = (fabsf(c0 - m0) <= s0) && (fabsf(c1 - m1) <= s1) && (fabsf(c2 - m2) <= s2);
            if (in) { cnt += 1.f; a0 += c0; a1 += c1; a2 += c2; }
        }
        float inv = __fdividef(1.0f, cnt + 1e-6f);
        float w0 = a0 * inv, w1 = a1 * inv, w2 = a2 * inv;
        voted[tid][0] = w0; voted[tid][1] = w1; voted[tid][2] = w2;
        long long vo = ((long long)b * NKP + tid) * 3;
        outV[vo + 0] = w0; outV[vo + 1] = w1; outV[vo + 2] = w2;
    }
    __syncthreads();

    // ---------------- Kabsch + 3x3 SVD (thread 0, fp32 fast-math) ----------------
    if (tid == 0) {
        const float* mb = mesh + (long long)b * NKP * 3;
        float cA[3] = {0, 0, 0}, cB[3] = {0, 0, 0};
#pragma unroll
        for (int i = 0; i < NKP; i++) {
            cA[0] += mb[i * 3 + 0]; cA[1] += mb[i * 3 + 1]; cA[2] += mb[i * 3 + 2];
            cB[0] += voted[i][0];   cB[1] += voted[i][1];   cB[2] += voted[i][2];
        }
        const float inv9 = 1.0f / 9.0f;
        cA[0] *= inv9; cA[1] *= inv9; cA[2] *= inv9;
        cB[0] *= inv9; cB[1] *= inv9; cB[2] *= inv9;

        float H[3][3] = {{0,0,0},{0,0,0},{0,0,0}};
#pragma unroll
        for (int i = 0; i < NKP; i++) {
            float am[3] = {mb[i*3+0] - cA[0], mb[i*3+1] - cA[1], mb[i*3+2] - cA[2]};
            float bm[3] = {voted[i][0] - cB[0], voted[i][1] - cB[1], voted[i][2] - cB[2]};
#pragma unroll
            for (int r = 0; r < 3; r++)
#pragma unroll
                for (int c = 0; c < 3; c++)
                    H[r][c] += am[r] * bm[c];
        }

        float K[3][3];
#pragma unroll
        for (int r = 0; r < 3; r++)
#pragma unroll
            for (int c = 0; c < 3; c++)
                K[r][c] = H[0][r]*H[0][c] + H[1][r]*H[1][c] + H[2][r]*H[2][c];

        float V[3][3] = {{1,0,0},{0,1,0},{0,0,1}};
        const float tr = K[0][0] + K[1][1] + K[2][2];
        const float tol = 1e-12f * tr * tr + 1e-30f;   // reachable in fp32

        const int PP[3] = {0, 0, 1};
        const int QQ[3] = {1, 2, 2};
#pragma unroll 1
        for (int sweep = 0; sweep < 6; sweep++) {
            float off = K[0][1]*K[0][1] + K[0][2]*K[0][2] + K[1][2]*K[1][2];
            if (off < tol) break;
#pragma unroll
            for (int pr = 0; pr < 3; pr++) {
                int p = PP[pr], q = QQ[pr];
                float apq = K[p][q];
                if (apq == 0.0f) continue;
                float theta = __fdividef(K[q][q] - K[p][p], 2.0f * apq);
                float t2p1  = theta * theta + 1.0f;
                float rs    = __frsqrt_rn(t2p1);        // 1/sqrt(theta^2+1)
                float sq    = t2p1 * rs;                // sqrt(theta^2+1)
                float t = __fdividef((theta >= 0.0f) ? 1.0f : -1.0f, fabsf(theta) + sq);
                float cc = __frsqrt_rn(t * t + 1.0f);
                float ss = t * cc;
                K[p][p] -= t * apq;
                K[q][q] += t * apq;
                K[p][q] = 0.0f; K[q][p] = 0.0f;
                int r3 = 3 - p - q;
                float krp = K[r3][p], krq = K[r3][q];
                K[r3][p] = cc*krp - ss*krq;  K[p][r3] = K[r3][p];
                K[r3][q] = ss*krp + cc*krq;  K[q][r3] = K[r3][q];
#pragma unroll
                for (int k = 0; k < 3; k++) {
                    float vp = V[k][p], vq = V[k][q];
                    V[k][p] = cc*vp - ss*vq;
                    V[k][q] = ss*vp + cc*vq;
                }
            }
        }

        // sort eigenvalues descending
        int ord[3] = {0, 1, 2};
#pragma unroll
        for (int i = 0; i < 2; i++)
#pragma unroll
            for (int j = i + 1; j < 3; j++)
                if (K[ord[j]][ord[j]] > K[ord[i]][ord[i]]) { int t2 = ord[i]; ord[i] = ord[j]; ord[j] = t2; }

        float v1[3], v2[3], v3[3];
#pragma unroll
        for (int c = 0; c < 3; c++) { v1[c] = V[c][ord[0]]; v2[c] = V[c][ord[1]]; v3[c] = V[c][ord[2]]; }

        float u1[3], u2[3], u3[3];
#pragma unroll
        for (int r = 0; r < 3; r++) u1[r] = H[r][0]*v1[0] + H[r][1]*v1[1] + H[r][2]*v1[2];
        float d1 = u1[0]*u1[0] + u1[1]*u1[1] + u1[2]*u1[2];
        float in1 = (d1 > 1e-30f) ? __frsqrt_rn(d1) : 0.0f;
        u1[0] *= in1; u1[1] *= in1; u1[2] *= in1;

#pragma unroll
        for (int r = 0; r < 3; r++) u2[r] = H[r][0]*v2[0] + H[r][1]*v2[1] + H[r][2]*v2[2];
        float d12 = u2[0]*u1[0] + u2[1]*u1[1] + u2[2]*u1[2];
        u2[0] -= d12 * u1[0]; u2[1] -= d12 * u1[1]; u2[2] -= d12 * u1[2];
        float d2 = u2[0]*u2[0] + u2[1]*u2[1] + u2[2]*u2[2];
        float in2 = (d2 > 1e-30f) ? __frsqrt_rn(d2) : 0.0f;
        u2[0] *= in2; u2[1] *= in2; u2[2] *= in2;

        u3[0] = u1[1]*u2[2] - u1[2]*u2[1];
        u3[1] = u1[2]*u2[0] - u1[0]*u2[2];
        u3[2] = u1[0]*u2[1] - u1[1]*u2[0];

        float R[3][3];
#pragma unroll
        for (int r = 0; r < 3; r++)
#pragma unroll
            for (int c = 0; c < 3; c++)
                R[r][c] = v1[r]*u1[c] + v2[r]*u2[c] + v3[r]*u3[c];

        float det = R[0][0]*(R[1][1]*R[2][2] - R[1][2]*R[2][1])
                  - R[0][1]*(R[1][0]*R[2][2] - R[1][2]*R[2][0])
                  + R[0][2]*(R[1][0]*R[2][1] - R[1][1]*R[2][0]);
        if (det < 0.0f) {
#pragma unroll
            for (int r = 0; r < 3; r++)
#pragma unroll
                for (int c = 0; c < 3; c++)
                    R[r][c] -= 2.0f * v3[r] * u3[c];
        }

        long long ro = (long long)b * 9;
#pragma unroll
        for (int r = 0; r < 3; r++)
#pragma unroll
            for (int c = 0; c < 3; c++)
                outR[ro + r*3 + c] = R[r][c];

        long long to = (long long)b * 3;
#pragma unroll
        for (int c = 0; c < 3; c++) {
            float tc = cB[c] - (R[c][0]*cA[0] + R[c][1]*cA[1] + R[c][2]*cA[2]);
            outT[to + c] = tc;
        }
    }
}

extern "C" void kernel_launch(void* const* d_in, const int* in_sizes, int n_in,
                              void* d_out, int out_size)
{
    const float* pcld = (const float*)d_in[0];  // [b,n,3]
    const float* kpts = (const float*)d_in[1];  // [b,n,8,3]
    const float* cpt  = (const float*)d_in[2];  // [b,n,1,3]
    const float* seg  = (const float*)d_in[3];  // [b,n,1]
    const float* mesh = (const float*)d_in[4];  // [b,9,3]

    int b = in_sizes[4] / 27;       // mesh is b*9*3
    int n = in_sizes[3] / b;        // seg is b*n

    float* out  = (float*)d_out;
    float* outR = out;                      // b*9
    float* outT = out + (long long)b * 9;   // b*3
    float* outV = out + (long long)b * 12;  // b*27

    pose_fused_kernel<<<b, TPB>>>(pcld, kpts, cpt, seg, mesh, outR, outT, outV, n);
}

// round 4
// speedup vs baseline: 4.5147x; 1.8284x over previous
#include <cuda_runtime.h>
#include <math.h>

#define TPB  256
#define KC   10      // n_point_candidate
#define NKP  9       // 8 keypoints + 1 center
#define CAP  2048    // candidate overflow capacity (expected ~11 used)

__global__ __launch_bounds__(TPB)
void pose_fused_kernel(const float* __restrict__ pcld,
                       const float* __restrict__ kpts,
                       const float* __restrict__ cpt,
                       const float* __restrict__ seg,
                       const float* __restrict__ mesh,
                       float* __restrict__ outR,
                       float* __restrict__ outT,
                       float* __restrict__ outV,
                       int n)
{
    const int b   = blockIdx.x;
    const int tid = threadIdx.x;

    __shared__ float gmax[64];
    __shared__ float sT;
    __shared__ int   cnt;
    __shared__ float cv[CAP];
    __shared__ int   ci[CAP];
    __shared__ int   topi[KC];
    __shared__ float cand[NKP][KC][3];
    __shared__ float voted[NKP][3];

    if (tid == 0) cnt = 0;

    const float*  segb = seg + (long long)b * n;
    const int     nf4  = n >> 2;
    const float4* seg4 = (const float4*)segb;

    // ---------------- pass 1: per-thread max (pure MLP, no dependent work) ----
    float m = -INFINITY;
    for (int i4 = tid; i4 < nf4; i4 += TPB) {
        float4 v = seg4[i4];
        m = fmaxf(m, fmaxf(fmaxf(v.x, v.y), fmaxf(v.z, v.w)));
    }
    for (int i = (nf4 << 2) + tid; i < n; i += TPB)
        m = fmaxf(m, segb[i]);

    // reduce to 64 group-maxes (groups of 4 adjacent lanes)
    m = fmaxf(m, __shfl_xor_sync(0xFFFFFFFFu, m, 1));
    m = fmaxf(m, __shfl_xor_sync(0xFFFFFFFFu, m, 2));
    if ((tid & 3) == 0) gmax[tid >> 2] = m;
    __syncthreads();

    // threshold T = 10th-largest group-max (rank 9 in total order).
    // Guarantees: >=10 distinct elements >= T, and global-10th >= T.
    if (tid < 64) {
        float v = gmax[tid];
        int rank = 0;
#pragma unroll 8
        for (int j = 0; j < 64; j++) {
            float vj = gmax[j];
            rank += (vj > v) || (vj == v && j < tid);
        }
        if (rank == KC - 1) sT = v;
    }
    __syncthreads();
    const float T = sT;

    // ---------------- pass 2: collect values >= T (L1-resident rescan) -------
    for (int i4 = tid; i4 < nf4; i4 += TPB) {
        float4 v = seg4[i4];
        float xs[4] = {v.x, v.y, v.z, v.w};
#pragma unroll
        for (int c = 0; c < 4; c++) {
            if (xs[c] >= T) {
                int s = atomicAdd(&cnt, 1);
                if (s < CAP) { cv[s] = xs[c]; ci[s] = (i4 << 2) + c; }
            }
        }
    }
    for (int i = (nf4 << 2) + tid; i < n; i += TPB) {
        float x = segb[i];
        if (x >= T) {
            int s = atomicAdd(&cnt, 1);
            if (s < CAP) { cv[s] = x; ci[s] = i; }
        }
    }
    __syncthreads();

    // exact top-10 set by rank-counting among the few candidates
    {
        int mC = min(cnt, CAP);
        for (int i = tid; i < mC; i += TPB) {
            float v = cv[i]; int id = ci[i];
            int rank = 0;
            for (int j = 0; j < mC; j++) {
                float vj = cv[j];
                rank += (vj > v) || (vj == v && ci[j] < id);
            }
            if (rank < KC) topi[rank] = id;
        }
    }
    __syncthreads();

    // ---------------- build candidates (90 threads) ----------------
    if (tid < NKP * KC) {
        int i  = tid / KC;           // keypoint
        int j  = tid % KC;           // candidate
        int id = topi[j];
        const float* p = pcld + ((long long)b * n + id) * 3;
        const float* o = (i < 8)
            ? (kpts + (((long long)b * n + id) * 8 + i) * 3)
            : (cpt  + ((long long)b * n + id) * 3);
        cand[i][j][0] = p[0] + o[0];
        cand[i][j][1] = p[1] + o[1];
        cand[i][j][2] = p[2] + o[2];
    }
    __syncthreads();

    // ---------------- clustering with std filter (9 threads) ----------------
    if (tid < NKP) {
        float m0 = 0.f, m1 = 0.f, m2 = 0.f;
#pragma unroll
        for (int j = 0; j < KC; j++) { m0 += cand[tid][j][0]; m1 += cand[tid][j][1]; m2 += cand[tid][j][2]; }
        m0 *= 0.1f; m1 *= 0.1f; m2 *= 0.1f;
        float v0 = 0.f, v1 = 0.f, v2 = 0.f;
#pragma unroll
        for (int j = 0; j < KC; j++) {
            float d0 = cand[tid][j][0] - m0, d1 = cand[tid][j][1] - m1, d2 = cand[tid][j][2] - m2;
            v0 += d0 * d0; v1 += d1 * d1; v2 += d2 * d2;
        }
        float s0 = sqrtf(v0 * 0.1f), s1 = sqrtf(v1 * 0.1f), s2 = sqrtf(v2 * 0.1f);
        float a0 = 0.f, a1 = 0.f, a2 = 0.f, cc = 0.f;
#pragma unroll
        for (int j = 0; j < KC; j++) {
            float c0 = cand[tid][j][0], c1 = cand[tid][j][1], c2 = cand[tid][j][2];
            bool in = (fabsf(c0 - m0) <= s0) && (fabsf(c1 - m1) <= s1) && (fabsf(c2 - m2) <= s2);
            if (in) { cc += 1.f; a0 += c0; a1 += c1; a2 += c2; }
        }
        float inv = __fdividef(1.0f, cc + 1e-6f);
        float w0 = a0 * inv, w1 = a1 * inv, w2 = a2 * inv;
        voted[tid][0] = w0; voted[tid][1] = w1; voted[tid][2] = w2;
        long long vo = ((long long)b * NKP + tid) * 3;
        outV[vo + 0] = w0; outV[vo + 1] = w1; outV[vo + 2] = w2;
    }
    __syncthreads();

    // ---------------- Kabsch + 3x3 SVD (thread 0, fp32 fast-math) ----------------
    if (tid == 0) {
        const float* mb = mesh + (long long)b * NKP * 3;
        float cA[3] = {0, 0, 0}, cB[3] = {0, 0, 0};
#pragma unroll
        for (int i = 0; i < NKP; i++) {
            cA[0] += mb[i * 3 + 0]; cA[1] += mb[i * 3 + 1]; cA[2] += mb[i * 3 + 2];
            cB[0] += voted[i][0];   cB[1] += voted[i][1];   cB[2] += voted[i][2];
        }
        const float inv9 = 1.0f / 9.0f;
        cA[0] *= inv9; cA[1] *= inv9; cA[2] *= inv9;
        cB[0] *= inv9; cB[1] *= inv9; cB[2] *= inv9;

        float H[3][3] = {{0,0,0},{0,0,0},{0,0,0}};
#pragma unroll
        for (int i = 0; i < NKP; i++) {
            float am[3] = {mb[i*3+0] - cA[0], mb[i*3+1] - cA[1], mb[i*3+2] - cA[2]};
            float bm[3] = {voted[i][0] - cB[0], voted[i][1] - cB[1], voted[i][2] - cB[2]};
#pragma unroll
            for (int r = 0; r < 3; r++)
#pragma unroll
                for (int c = 0; c < 3; c++)
                    H[r][c] += am[r] * bm[c];
        }

        float K[3][3];
#pragma unroll
        for (int r = 0; r < 3; r++)
#pragma unroll
            for (int c = 0; c < 3; c++)
                K[r][c] = H[0][r]*H[0][c] + H[1][r]*H[1][c] + H[2][r]*H[2][c];

        float V[3][3] = {{1,0,0},{0,1,0},{0,0,1}};
        const float tr = K[0][0] + K[1][1] + K[2][2];
        const float tol = 1e-12f * tr * tr + 1e-30f;

        const int PP[3] = {0, 0, 1};
        const int QQ[3] = {1, 2, 2};
#pragma unroll 1
        for (int sweep = 0; sweep < 6; sweep++) {
            float off = K[0][1]*K[0][1] + K[0][2]*K[0][2] + K[1][2]*K[1][2];
            if (off < tol) break;
#pragma unroll
            for (int pr = 0; pr < 3; pr++) {
                int p = PP[pr], q = QQ[pr];
                float apq = K[p][q];
                if (apq == 0.0f) continue;
                float theta = __fdividef(K[q][q] - K[p][p], 2.0f * apq);
                float t2p1  = theta * theta + 1.0f;
                float rs    = __frsqrt_rn(t2p1);
                float sq    = t2p1 * rs;
                float t = __fdividef((theta >= 0.0f) ? 1.0f : -1.0f, fabsf(theta) + sq);
                float c2 = __frsqrt_rn(t * t + 1.0f);
                float ss = t * c2;
                K[p][p] -= t * apq;
                K[q][q] += t * apq;
                K[p][q] = 0.0f; K[q][p] = 0.0f;
                int r3 = 3 - p - q;
                float krp = K[r3][p], krq = K[r3][q];
                K[r3][p] = c2*krp - ss*krq;  K[p][r3] = K[r3][p];
                K[r3][q] = ss*krp + c2*krq;  K[q][r3] = K[r3][q];
#pragma unroll
                for (int k = 0; k < 3; k++) {
                    float vp = V[k][p], vq = V[k][q];
                    V[k][p] = c2*vp - ss*vq;
                    V[k][q] = ss*vp + c2*vq;
                }
            }
        }

        int ord[3] = {0, 1, 2};
#pragma unroll
        for (int i = 0; i < 2; i++)
#pragma unroll
            for (int j = i + 1; j < 3; j++)
                if (K[ord[j]][ord[j]] > K[ord[i]][ord[i]]) { int t2 = ord[i]; ord[i] = ord[j]; ord[j] = t2; }

        float v1[3], v2[3], v3[3];
#pragma unroll
        for (int c = 0; c < 3; c++) { v1[c] = V[c][ord[0]]; v2[c] = V[c][ord[1]]; v3[c] = V[c][ord[2]]; }

        float u1[3], u2[3], u3[3];
#pragma unroll
        for (int r = 0; r < 3; r++) u1[r] = H[r][0]*v1[0] + H[r][1]*v1[1] + H[r][2]*v1[2];
        float d1 = u1[0]*u1[0] + u1[1]*u1[1] + u1[2]*u1[2];
        float in1 = (d1 > 1e-30f) ? __frsqrt_rn(d1) : 0.0f;
        u1[0] *= in1; u1[1] *= in1; u1[2] *= in1;

#pragma unroll
        for (int r = 0; r < 3; r++) u2[r] = H[r][0]*v2[0] + H[r][1]*v2[1] + H[r][2]*v2[2];
        float d12 = u2[0]*u1[0] + u2[1]*u1[1] + u2[2]*u1[2];
        u2[0] -= d12 * u1[0]; u2[1] -= d12 * u1[1]; u2[2] -= d12 * u1[2];
        float d2 = u2[0]*u2[0] + u2[1]*u2[1] + u2[2]*u2[2];
        float in2 = (d2 > 1e-30f) ? __frsqrt_rn(d2) : 0.0f;
        u2[0] *= in2; u2[1] *= in2; u2[2] *= in2;

        u3[0] = u1[1]*u2[2] - u1[2]*u2[1];
        u3[1] = u1[2]*u2[0] - u1[0]*u2[2];
        u3[2] = u1[0]*u2[1] - u1[1]*u2[0];

        float R[3][3];
#pragma unroll
        for (int r = 0; r < 3; r++)
#pragma unroll
            for (int c = 0; c < 3; c++)
                R[r][c] = v1[r]*u1[c] + v2[r]*u2[c] + v3[r]*u3[c];

        float det = R[0][0]*(R[1][1]*R[2][2] - R[1][2]*R[2][1])
                  - R[0][1]*(R[1][0]*R[2][2] - R[1][2]*R[2][0])
                  + R[0][2]*(R[1][0]*R[2][1] - R[1][1]*R[2][0]);
        if (det < 0.0f) {
#pragma unroll
            for (int r = 0; r < 3; r++)
#pragma unroll
                for (int c = 0; c < 3; c++)
                    R[r][c] -= 2.0f * v3[r] * u3[c];
        }

        long long ro = (long long)b * 9;
#pragma unroll
        for (int r = 0; r < 3; r++)
#pragma unroll
            for (int c = 0; c < 3; c++)
                outR[ro + r*3 + c] = R[r][c];

        long long to = (long long)b * 3;
#pragma unroll
        for (int c = 0; c < 3; c++) {
            float tc = cB[c] - (R[c][0]*cA[0] + R[c][1]*cA[1] + R[c][2]*cA[2]);
            outT[to + c] = tc;
        }
    }
}

extern "C" void kernel_launch(void* const* d_in, const int* in_sizes, int n_in,
                              void* d_out, int out_size)
{
    const float* pcld = (const float*)d_in[0];  // [b,n,3]
    const float* kpts = (const float*)d_in[1];  // [b,n,8,3]
    const float* cpt  = (const float*)d_in[2];  // [b,n,1,3]
    const float* seg  = (const float*)d_in[3];  // [b,n,1]
    const float* mesh = (const float*)d_in[4];  // [b,9,3]

    int b = in_sizes[4] / 27;       // mesh is b*9*3
    int n = in_sizes[3] / b;        // seg is b*n

    float* out  = (float*)d_out;
    float* outR = out;                      // b*9
    float* outT = out + (long long)b * 9;   // b*3
    float* outV = out + (long long)b * 12;  // b*27

    pose_fused_kernel<<<b, TPB>>>(pcld, kpts, cpt, seg, mesh, outR, outT, outV, n);
}

// round 6
// speedup vs baseline: 5.4985x; 1.2179x over previous
#include <cuda_runtime.h>
#include <math.h>

#define TPB  512
#define NW   (TPB / 32)   // 16 warps
#define KC   10           // n_point_candidate
#define NKP  9            // 8 keypoints + 1 center
#define CAP  1024         // collected-candidate capacity (expected ~12 used)
#define REGC 6            // float4 per thread held in registers (n <= TPB*REGC*4)

__global__ __launch_bounds__(TPB)
void pose_fused_kernel(const float* __restrict__ pcld,
                       const float* __restrict__ kpts,
                       const float* __restrict__ cpt,
                       const float* __restrict__ seg,
                       const float* __restrict__ mesh,
                       float* __restrict__ outR,
                       float* __restrict__ outT,
                       float* __restrict__ outV,
                       int n)
{
    const int b   = blockIdx.x;
    const int tid = threadIdx.x;

    __shared__ float wmax[NW];
    __shared__ float sT;
    __shared__ int   cnt;
    __shared__ float cv[CAP];
    __shared__ int   ci[CAP];
    __shared__ int   topi[KC];
    __shared__ float cand[NKP][KC][3];
    __shared__ float voted[NKP][3];

    if (tid == 0) cnt = 0;

    const float*  segb = seg + (long long)b * n;
    const int     nf4  = n >> 2;
    const float4* seg4 = (const float4*)segb;
    const int     regEnd = TPB * REGC;      // float4 indices covered by registers

    // ---- single load pass: everything into registers (6 independent loads) ----
    float4 buf[REGC];
#pragma unroll
    for (int j = 0; j < REGC; j++) {
        int i4 = tid + j * TPB;
        buf[j] = (i4 < nf4) ? seg4[i4]
                            : make_float4(-INFINITY, -INFINITY, -INFINITY, -INFINITY);
    }

    float m = -INFINITY;
#pragma unroll
    for (int j = 0; j < REGC; j++)
        m = fmaxf(m, fmaxf(fmaxf(buf[j].x, buf[j].y), fmaxf(buf[j].z, buf[j].w)));

    // fallback for n beyond register capacity (not taken at n = 12288)
    for (int i4 = regEnd + tid; i4 < nf4; i4 += TPB) {
        float4 v = seg4[i4];
        m = fmaxf(m, fmaxf(fmaxf(v.x, v.y), fmaxf(v.z, v.w)));
    }
    for (int i = (nf4 << 2) + tid; i < n; i += TPB)
        m = fmaxf(m, segb[i]);

    // ---- warp max -> 16 group maxes ----
#pragma unroll
    for (int d = 16; d > 0; d >>= 1)
        m = fmaxf(m, __shfl_xor_sync(0xFFFFFFFFu, m, d));
    if ((tid & 31) == 0) wmax[tid >> 5] = m;
    __syncthreads();

    // threshold T = 10th-largest warp max (rank KC-1). 10 disjoint warps each
    // hold >=1 element >= T  =>  global top-10 are all >= T.
    if (tid < NW) {
        float v = wmax[tid];
        int rank = 0;
#pragma unroll
        for (int j = 0; j < NW; j++) {
            float vj = wmax[j];
            rank += (vj > v) || (vj == v && j < tid);
        }
        if (rank == KC - 1) sT = v;
    }
    __syncthreads();
    const float T = sT;

    // ---- filter pass from REGISTERS (no memory traffic) ----
#pragma unroll
    for (int j = 0; j < REGC; j++) {
        int i4 = tid + j * TPB;
        float xs[4] = {buf[j].x, buf[j].y, buf[j].z, buf[j].w};
#pragma unroll
        for (int c = 0; c < 4; c++) {
            if (xs[c] >= T) {
                int s = atomicAdd(&cnt, 1);
                if (s < CAP) { cv[s] = xs[c]; ci[s] = (i4 << 2) + c; }
            }
        }
    }
    // fallback ranges rescan memory (not taken at n = 12288)
    for (int i4 = regEnd + tid; i4 < nf4; i4 += TPB) {
        float4 v = seg4[i4];
        float xs[4] = {v.x, v.y, v.z, v.w};
#pragma unroll
        for (int c = 0; c < 4; c++) {
            if (xs[c] >= T) {
                int s = atomicAdd(&cnt, 1);
                if (s < CAP) { cv[s] = xs[c]; ci[s] = (i4 << 2) + c; }
            }
        }
    }
    for (int i = (nf4 << 2) + tid; i < n; i += TPB) {
        float x = segb[i];
        if (x >= T) {
            int s = atomicAdd(&cnt, 1);
            if (s < CAP) { cv[s] = x; ci[s] = i; }
        }
    }
    __syncthreads();

    // exact top-10 set by rank-counting among the ~12 collected
    {
        int mC = min(cnt, CAP);
        for (int i = tid; i < mC; i += TPB) {
            float v = cv[i]; int id = ci[i];
            int rank = 0;
            for (int j = 0; j < mC; j++) {
                float vj = cv[j];
                rank += (vj > v) || (vj == v && ci[j] < id);
            }
            if (rank < KC) topi[rank] = id;
        }
    }
    __syncthreads();

    // ---------------- build candidates (90 threads) ----------------
    if (tid < NKP * KC) {
        int i  = tid / KC;           // keypoint
        int j  = tid % KC;           // candidate
        int id = topi[j];
        const float* p = pcld + ((long long)b * n + id) * 3;
        const float* o = (i < 8)
            ? (kpts + (((long long)b * n + id) * 8 + i) * 3)
            : (cpt  + ((long long)b * n + id) * 3);
        cand[i][j][0] = p[0] + o[0];
        cand[i][j][1] = p[1] + o[1];
        cand[i][j][2] = p[2] + o[2];
    }
    __syncthreads();

    // ---------------- clustering with std filter (9 threads) ----------------
    if (tid < NKP) {
        float m0 = 0.f, m1 = 0.f, m2 = 0.f;
#pragma unroll
        for (int j = 0; j < KC; j++) { m0 += cand[tid][j][0]; m1 += cand[tid][j][1]; m2 += cand[tid][j][2]; }
        m0 *= 0.1f; m1 *= 0.1f; m2 *= 0.1f;
        float v0 = 0.f, v1 = 0.f, v2 = 0.f;
#pragma unroll
        for (int j = 0; j < KC; j++) {
            float d0 = cand[tid][j][0] - m0, d1 = cand[tid][j][1] - m1, d2 = cand[tid][j][2] - m2;
            v0 += d0 * d0; v1 += d1 * d1; v2 += d2 * d2;
        }
        float s0 = sqrtf(v0 * 0.1f), s1 = sqrtf(v1 * 0.1f), s2 = sqrtf(v2 * 0.1f);
        float a0 = 0.f, a1 = 0.f, a2 = 0.f, cc = 0.f;
#pragma unroll
        for (int j = 0; j < KC; j++) {
            float c0 = cand[tid][j][0], c1 = cand[tid][j][1], c2 = cand[tid][j][2];
            bool in = (fabsf(c0 - m0) <= s0) && (fabsf(c1 - m1) <= s1) && (fabsf(c2 - m2) <= s2);
            if (in) { cc += 1.f; a0 += c0; a1 += c1; a2 += c2; }
        }
        float inv = __fdividef(1.0f, cc + 1e-6f);
        float w0 = a0 * inv, w1 = a1 * inv, w2 = a2 * inv;
        voted[tid][0] = w0; voted[tid][1] = w1; voted[tid][2] = w2;
        long long vo = ((long long)b * NKP + tid) * 3;
        outV[vo + 0] = w0; outV[vo + 1] = w1; outV[vo + 2] = w2;
    }
    __syncthreads();

    // ---------------- Kabsch + 3x3 SVD (thread 0, fp32 fast-math) ----------------
    if (tid == 0) {
        const float* mb = mesh + (long long)b * NKP * 3;
        float cA[3] = {0, 0, 0}, cB[3] = {0, 0, 0};
#pragma unroll
        for (int i = 0; i < NKP; i++) {
            cA[0] += mb[i * 3 + 0]; cA[1] += mb[i * 3 + 1]; cA[2] += mb[i * 3 + 2];
            cB[0] += voted[i][0];   cB[1] += voted[i][1];   cB[2] += voted[i][2];
        }
        const float inv9 = 1.0f / 9.0f;
        cA[0] *= inv9; cA[1] *= inv9; cA[2] *= inv9;
        cB[0] *= inv9; cB[1] *= inv9; cB[2] *= inv9;

        float H[3][3] = {{0,0,0},{0,0,0},{0,0,0}};
#pragma unroll
        for (int i = 0; i < NKP; i++) {
            float am[3] = {mb[i*3+0] - cA[0], mb[i*3+1] - cA[1], mb[i*3+2] - cA[2]};
            float bm[3] = {voted[i][0] - cB[0], voted[i][1] - cB[1], voted[i][2] - cB[2]};
#pragma unroll
            for (int r = 0; r < 3; r++)
#pragma unroll
                for (int c = 0; c < 3; c++)
                    H[r][c] += am[r] * bm[c];
        }

        float K[3][3];
#pragma unroll
        for (int r = 0; r < 3; r++)
#pragma unroll
            for (int c = 0; c < 3; c++)
                K[r][c] = H[0][r]*H[0][c] + H[1][r]*H[1][c] + H[2][r]*H[2][c];

        float V[3][3] = {{1,0,0},{0,1,0},{0,0,1}};
        const float tr = K[0][0] + K[1][1] + K[2][2];
        const float tol = 1e-12f * tr * tr + 1e-30f;

        const int PP[3] = {0, 0, 1};
        const int QQ[3] = {1, 2, 2};
#pragma unroll 1
        for (int sweep = 0; sweep < 6; sweep++) {
            float off = K[0][1]*K[0][1] + K[0][2]*K[0][2] + K[1][2]*K[1][2];
            if (off < tol) break;
#pragma unroll
            for (int pr = 0; pr < 3; pr++) {
                int p = PP[pr], q = QQ[pr];
                float apq = K[p][q];
                if (apq == 0.0f) continue;
                float theta = __fdividef(K[q][q] - K[p][p], 2.0f * apq);
                float t2p1  = theta * theta + 1.0f;
                float rs    = __frsqrt_rn(t2p1);
                float sq    = t2p1 * rs;
                float t = __fdividef((theta >= 0.0f) ? 1.0f : -1.0f, fabsf(theta) + sq);
                float c2 = __frsqrt_rn(t * t + 1.0f);
                float ss = t * c2;
                K[p][p] -= t * apq;
                K[q][q] += t * apq;
                K[p][q] = 0.0f; K[q][p] = 0.0f;
                int r3 = 3 - p - q;
                float krp = K[r3][p], krq = K[r3][q];
                K[r3][p] = c2*krp - ss*krq;  K[p][r3] = K[r3][p];
                K[r3][q] = ss*krp + c2*krq;  K[q][r3] = K[r3][q];
#pragma unroll
                for (int k = 0; k < 3; k++) {
                    float vp = V[k][p], vq = V[k][q];
                    V[k][p] = c2*vp - ss*vq;
                    V[k][q] = ss*vp + c2*vq;
                }
            }
        }

        int ord[3] = {0, 1, 2};
#pragma unroll
        for (int i = 0; i < 2; i++)
#pragma unroll
            for (int j = i + 1; j < 3; j++)
                if (K[ord[j]][ord[j]] > K[ord[i]][ord[i]]) { int t2 = ord[i]; ord[i] = ord[j]; ord[j] = t2; }

        float v1[3], v2[3], v3[3];
#pragma unroll
        for (int c = 0; c < 3; c++) { v1[c] = V[c][ord[0]]; v2[c] = V[c][ord[1]]; v3[c] = V[c][ord[2]]; }

        float u1[3], u2[3], u3[3];
#pragma unroll
        for (int r = 0; r < 3; r++) u1[r] = H[r][0]*v1[0] + H[r][1]*v1[1] + H[r][2]*v1[2];
        float d1 = u1[0]*u1[0] + u1[1]*u1[1] + u1[2]*u1[2];
        float in1 = (d1 > 1e-30f) ? __frsqrt_rn(d1) : 0.0f;
        u1[0] *= in1; u1[1] *= in1; u1[2] *= in1;

#pragma unroll
        for (int r = 0; r < 3; r++) u2[r] = H[r][0]*v2[0] + H[r][1]*v2[1] + H[r][2]*v2[2];
        float d12 = u2[0]*u1[0] + u2[1]*u1[1] + u2[2]*u1[2];
        u2[0] -= d12 * u1[0]; u2[1] -= d12 * u1[1]; u2[2] -= d12 * u1[2];
        float d2 = u2[0]*u2[0] + u2[1]*u2[1] + u2[2]*u2[2];
        float in2 = (d2 > 1e-30f) ? __frsqrt_rn(d2) : 0.0f;
        u2[0] *= in2; u2[1] *= in2; u2[2] *= in2;

        u3[0] = u1[1]*u2[2] - u1[2]*u2[1];
        u3[1] = u1[2]*u2[0] - u1[0]*u2[2];
        u3[2] = u1[0]*u2[1] - u1[1]*u2[0];

        float R[3][3];
#pragma unroll
        for (int r = 0; r < 3; r++)
#pragma unroll
            for (int c = 0; c < 3; c++)
                R[r][c] = v1[r]*u1[c] + v2[r]*u2[c] + v3[r]*u3[c];

        float det = R[0][0]*(R[1][1]*R[2][2] - R[1][2]*R[2][1])
                  - R[0][1]*(R[1][0]*R[2][2] - R[1][2]*R[2][0])
                  + R[0][2]*(R[1][0]*R[2][1] - R[1][1]*R[2][0]);
        if (det < 0.0f) {
#pragma unroll
            for (int r = 0; r < 3; r++)
#pragma unroll
                for (int c = 0; c < 3; c++)
                    R[r][c] -= 2.0f * v3[r] * u3[c];
        }

        long long ro = (long long)b * 9;
#pragma unroll
        for (int r = 0; r < 3; r++)
#pragma unroll
            for (int c = 0; c < 3; c++)
                outR[ro + r*3 + c] = R[r][c];

        long long to = (long long)b * 3;
#pragma unroll
        for (int c = 0; c < 3; c++) {
            float tc = cB[c] - (R[c][0]*cA[0] + R[c][1]*cA[1] + R[c][2]*cA[2]);
            outT[to + c] = tc;
        }
    }
}

extern "C" void kernel_launch(void* const* d_in, const int* in_sizes, int n_in,
                              void* d_out, int out_size)
{
    const float* pcld = (const float*)d_in[0];  // [b,n,3]
    const float* kpts = (const float*)d_in[1];  // [b,n,8,3]
    const float* cpt  = (const float*)d_in[2];  // [b,n,1,3]
    const float* seg  = (const float*)d_in[3];  // [b,n,1]
    const float* mesh = (const float*)d_in[4];  // [b,9,3]

    int b = in_sizes[4] / 27;       // mesh is b*9*3
    int n = in_sizes[3] / b;        // seg is b*n

    float* out  = (float*)d_out;
    float* outR = out;                      // b*9
    float* outT = out + (long long)b * 9;   // b*3
    float* outV = out + (long long)b * 12;  // b*27

    pose_fused_kernel<<<b, TPB>>>(pcld, kpts, cpt, seg, mesh, outR, outT, outV, n);
}

// round 8
// speedup vs baseline: 5.5818x; 1.0152x over previous
#include <cuda_runtime.h>
#include <math.h>

#define TPB  512
#define NW   (TPB / 32)   // 16 warps
#define KC   10           // n_point_candidate
#define NKP  9            // 8 keypoints + 1 center
#define CAP  1024         // collected-candidate capacity (expected ~12 used)
#define REGC 6            // float4 per thread held in registers (n <= TPB*REGC*4)

// order-preserving float -> uint key (works for all finite floats)
__device__ __forceinline__ unsigned fkey(float x) {
    unsigned u = __float_as_uint(x);
    return (u & 0x80000000u) ? ~u : (u | 0x80000000u);
}
__device__ __forceinline__ float funkey(unsigned k) {
    return __uint_as_float((k & 0x80000000u) ? (k & 0x7FFFFFFFu) : ~k);
}

// eigenvector of symmetric K for eigenvalue lam: largest cross product of rows of K-lam*I
__device__ __forceinline__ void eigvec3(const float K[3][3], float lam, float v[3]) {
    float a00 = K[0][0] - lam, a11 = K[1][1] - lam, a22 = K[2][2] - lam;
    float a01 = K[0][1], a02 = K[0][2], a12 = K[1][2];
    float c0x = a01*a12 - a02*a11, c0y = a02*a01 - a00*a12, c0z = a00*a11 - a01*a01;
    float c1x = a01*a22 - a02*a12, c1y = a02*a02 - a00*a22, c1z = a00*a12 - a01*a02;
    float c2x = a11*a22 - a12*a12, c2y = a12*a02 - a01*a22, c2z = a01*a12 - a11*a02;
    float n0 = c0x*c0x + c0y*c0y + c0z*c0z;
    float n1 = c1x*c1x + c1y*c1y + c1z*c1z;
    float n2 = c2x*c2x + c2y*c2y + c2z*c2z;
    float bx = c0x, by = c0y, bz = c0z, bn = n0;
    if (n1 > bn) { bx = c1x; by = c1y; bz = c1z; bn = n1; }
    if (n2 > bn) { bx = c2x; by = c2y; bz = c2z; bn = n2; }
    float inv = (bn > 1e-30f) ? __frsqrt_rn(bn) : 0.0f;
    v[0] = bx * inv; v[1] = by * inv; v[2] = bz * inv;
}

__global__ __launch_bounds__(TPB)
void pose_fused_kernel(const float* __restrict__ pcld,
                       const float* __restrict__ kpts,
                       const float* __restrict__ cpt,
                       const float* __restrict__ seg,
                       const float* __restrict__ mesh,
                       float* __restrict__ outR,
                       float* __restrict__ outT,
                       float* __restrict__ outV,
                       int n)
{
    const int b   = blockIdx.x;
    const int tid = threadIdx.x;

    __shared__ unsigned wmaxk[NW];
    __shared__ float sT;
    __shared__ int   cnt;
    __shared__ float smesh[NKP * 3];
    __shared__ float cv[CAP];
    __shared__ int   ci[CAP];
    __shared__ int   topi[KC];
    __shared__ float cand[NKP][KC][3];
    __shared__ float voted[NKP][3];

    // issue the tiny mesh load FIRST so its DRAM latency hides under the seg epoch
    if (tid < NKP * 3) smesh[tid] = mesh[(long long)b * NKP * 3 + tid];
    if (tid == 0) cnt = 0;

    const float*  segb = seg + (long long)b * n;
    const int     nf4  = n >> 2;
    const float4* seg4 = (const float4*)segb;
    const int     regEnd = TPB * REGC;      // float4 indices covered by registers

    // ---- single load pass: everything into registers (6 independent loads) ----
    float4 buf[REGC];
#pragma unroll
    for (int j = 0; j < REGC; j++) {
        int i4 = tid + j * TPB;
        buf[j] = (i4 < nf4) ? seg4[i4]
                            : make_float4(-INFINITY, -INFINITY, -INFINITY, -INFINITY);
    }

    float m = -INFINITY;
#pragma unroll
    for (int j = 0; j < REGC; j++)
        m = fmaxf(m, fmaxf(fmaxf(buf[j].x, buf[j].y), fmaxf(buf[j].z, buf[j].w)));

    // fallback for n beyond register capacity (not taken at n = 12288)
    for (int i4 = regEnd + tid; i4 < nf4; i4 += TPB) {
        float4 v = seg4[i4];
        m = fmaxf(m, fmaxf(fmaxf(v.x, v.y), fmaxf(v.z, v.w)));
    }
    for (int i = (nf4 << 2) + tid; i < n; i += TPB)
        m = fmaxf(m, segb[i]);

    // ---- warp max via single REDUX on order-preserving key ----
    unsigned mk = __reduce_max_sync(0xFFFFFFFFu, fkey(m));
    if ((tid & 31) == 0) wmaxk[tid >> 5] = mk;
    __syncthreads();

    // threshold T = 10th-largest warp max (rank KC-1). 10 disjoint warps each
    // hold >=1 element >= T  =>  global top-10 are all >= T.
    if (tid < NW) {
        unsigned v = wmaxk[tid];
        int rank = 0;
#pragma unroll
        for (int j = 0; j < NW; j++) {
            unsigned vj = wmaxk[j];
            rank += (vj > v) || (vj == v && j < tid);
        }
        if (rank == KC - 1) sT = funkey(v);
    }
    __syncthreads();
    const float T = sT;

    // ---- filter pass from REGISTERS (no memory traffic) ----
#pragma unroll
    for (int j = 0; j < REGC; j++) {
        int i4 = tid + j * TPB;
        float xs[4] = {buf[j].x, buf[j].y, buf[j].z, buf[j].w};
#pragma unroll
        for (int c = 0; c < 4; c++) {
            if (xs[c] >= T) {
                int s = atomicAdd(&cnt, 1);
                if (s < CAP) { cv[s] = xs[c]; ci[s] = (i4 << 2) + c; }
            }
        }
    }
    // fallback ranges rescan memory (not taken at n = 12288)
    for (int i4 = regEnd + tid; i4 < nf4; i4 += TPB) {
        float4 v = seg4[i4];
        float xs[4] = {v.x, v.y, v.z, v.w};
#pragma unroll
        for (int c = 0; c < 4; c++) {
            if (xs[c] >= T) {
                int s = atomicAdd(&cnt, 1);
                if (s < CAP) { cv[s] = xs[c]; ci[s] = (i4 << 2) + c; }
            }
        }
    }
    for (int i = (nf4 << 2) + tid; i < n; i += TPB) {
        float x = segb[i];
        if (x >= T) {
            int s = atomicAdd(&cnt, 1);
            if (s < CAP) { cv[s] = x; ci[s] = i; }
        }
    }
    __syncthreads();

    // exact top-10 set by rank-counting among the ~12 collected
    {
        int mC = min(cnt, CAP);
        for (int i = tid; i < mC; i += TPB) {
            float v = cv[i]; int id = ci[i];
            int rank = 0;
            for (int j = 0; j < mC; j++) {
                float vj = cv[j];
                rank += (vj > v) || (vj == v && ci[j] < id);
            }
            if (rank < KC) topi[rank] = id;
        }
    }
    __syncthreads();

    // ---------------- build candidates (90 threads) ----------------
    if (tid < NKP * KC) {
        int i  = tid / KC;           // keypoint
        int j  = tid % KC;           // candidate
        int id = topi[j];
        const float* p = pcld + ((long long)b * n + id) * 3;
        const float* o = (i < 8)
            ? (kpts + (((long long)b * n + id) * 8 + i) * 3)
            : (cpt  + ((long long)b * n + id) * 3);
        cand[i][j][0] = p[0] + o[0];
        cand[i][j][1] = p[1] + o[1];
        cand[i][j][2] = p[2] + o[2];
    }
    __syncthreads();

    // ---------------- clustering with std filter (9 threads) ----------------
    if (tid < NKP) {
        float m0 = 0.f, m1 = 0.f, m2 = 0.f;
#pragma unroll
        for (int j = 0; j < KC; j++) { m0 += cand[tid][j][0]; m1 += cand[tid][j][1]; m2 += cand[tid][j][2]; }
        m0 *= 0.1f; m1 *= 0.1f; m2 *= 0.1f;
        float v0 = 0.f, v1 = 0.f, v2 = 0.f;
#pragma unroll
        for (int j = 0; j < KC; j++) {
            float d0 = cand[tid][j][0] - m0, d1 = cand[tid][j][1] - m1, d2 = cand[tid][j][2] - m2;
            v0 += d0 * d0; v1 += d1 * d1; v2 += d2 * d2;
        }
        float s0 = sqrtf(v0 * 0.1f), s1 = sqrtf(v1 * 0.1f), s2 = sqrtf(v2 * 0.1f);
        float a0 = 0.f, a1 = 0.f, a2 = 0.f, cc = 0.f;
#pragma unroll
        for (int j = 0; j < KC; j++) {
            float c0 = cand[tid][j][0], c1 = cand[tid][j][1], c2 = cand[tid][j][2];
            bool in = (fabsf(c0 - m0) <= s0) && (fabsf(c1 - m1) <= s1) && (fabsf(c2 - m2) <= s2);
            if (in) { cc += 1.f; a0 += c0; a1 += c1; a2 += c2; }
        }
        float inv = __fdividef(1.0f, cc + 1e-6f);
        float w0 = a0 * inv, w1 = a1 * inv, w2 = a2 * inv;
        voted[tid][0] = w0; voted[tid][1] = w1; voted[tid][2] = w2;
        long long vo = ((long long)b * NKP + tid) * 3;
        outV[vo + 0] = w0; outV[vo + 1] = w1; outV[vo + 2] = w2;
    }
    __syncthreads();

    // ---------------- Kabsch + closed-form 3x3 eigen (thread 0) ----------------
    if (tid == 0) {
        float cA[3] = {0, 0, 0}, cB[3] = {0, 0, 0};
#pragma unroll
        for (int i = 0; i < NKP; i++) {
            cA[0] += smesh[i * 3 + 0]; cA[1] += smesh[i * 3 + 1]; cA[2] += smesh[i * 3 + 2];
            cB[0] += voted[i][0];      cB[1] += voted[i][1];      cB[2] += voted[i][2];
        }
        const float inv9 = 1.0f / 9.0f;
        cA[0] *= inv9; cA[1] *= inv9; cA[2] *= inv9;
        cB[0] *= inv9; cB[1] *= inv9; cB[2] *= inv9;

        float H[3][3] = {{0,0,0},{0,0,0},{0,0,0}};
#pragma unroll
        for (int i = 0; i < NKP; i++) {
            float am[3] = {smesh[i*3+0] - cA[0], smesh[i*3+1] - cA[1], smesh[i*3+2] - cA[2]};
            float bm[3] = {voted[i][0] - cB[0], voted[i][1] - cB[1], voted[i][2] - cB[2]};
#pragma unroll
            for (int r = 0; r < 3; r++)
#pragma unroll
                for (int c = 0; c < 3; c++)
                    H[r][c] += am[r] * bm[c];
        }

        // K = H^T H (symmetric, PSD)
        float K[3][3];
#pragma unroll
        for (int r = 0; r < 3; r++)
#pragma unroll
            for (int c = 0; c < 3; c++)
                K[r][c] = H[0][r]*H[0][c] + H[1][r]*H[1][c] + H[2][r]*H[2][c];

        // closed-form symmetric eigenvalues (Smith): e1 >= e2 >= e3
        float v1[3] = {1.f, 0.f, 0.f}, v2[3] = {0.f, 1.f, 0.f};
        {
            float q  = (K[0][0] + K[1][1] + K[2][2]) * (1.0f / 3.0f);
            float p1 = K[0][1]*K[0][1] + K[0][2]*K[0][2] + K[1][2]*K[1][2];
            float b0 = K[0][0] - q, b1 = K[1][1] - q, b2 = K[2][2] - q;
            float p2 = b0*b0 + b1*b1 + b2*b2 + 2.0f * p1;
            if (p2 > 1e-30f) {
                float pp   = p2 * (1.0f / 6.0f);
                float invp = __frsqrt_rn(pp);
                float p    = pp * invp;                 // sqrt(p2/6)
                // det(B)/2 with B = (K - qI)/p
                float detB = b0 * (b1*b2 - K[1][2]*K[1][2])
                           - K[0][1] * (K[0][1]*b2 - K[1][2]*K[0][2])
                           + K[0][2] * (K[0][1]*K[1][2] - b1*K[0][2]);
                float r = detB * 0.5f * invp * invp * invp;
                r = fminf(1.0f, fmaxf(-1.0f, r));
                float phi = acosf(r) * (1.0f / 3.0f);
                float e1 = q + 2.0f * p * __cosf(phi);
                float e3 = q + 2.0f * p * __cosf(phi + 2.0943951023931953f);
                float e2 = 3.0f * q - e1 - e3;
                eigvec3(K, e1, v1);
                eigvec3(K, e2, v2);
                // re-orthogonalize v2 against v1 (robust near-degenerate gaps)
                float d = v2[0]*v1[0] + v2[1]*v1[1] + v2[2]*v1[2];
                v2[0] -= d * v1[0]; v2[1] -= d * v1[1]; v2[2] -= d * v1[2];
                float nn = v2[0]*v2[0] + v2[1]*v2[1] + v2[2]*v2[2];
                float ii = (nn > 1e-30f) ? __frsqrt_rn(nn) : 0.0f;
                v2[0] *= ii; v2[1] *= ii; v2[2] *= ii;
            }
        }
        float v3[3] = { v1[1]*v2[2] - v1[2]*v2[1],
                        v1[2]*v2[0] - v1[0]*v2[2],
                        v1[0]*v2[1] - v1[1]*v2[0] };

        float u1[3], u2[3], u3[3];
#pragma unroll
        for (int r = 0; r < 3; r++) u1[r] = H[r][0]*v1[0] + H[r][1]*v1[1] + H[r][2]*v1[2];
        float d1 = u1[0]*u1[0] + u1[1]*u1[1] + u1[2]*u1[2];
        float in1 = (d1 > 1e-30f) ? __frsqrt_rn(d1) : 0.0f;
        u1[0] *= in1; u1[1] *= in1; u1[2] *= in1;

#pragma unroll
        for (int r = 0; r < 3; r++) u2[r] = H[r][0]*v2[0] + H[r][1]*v2[1] + H[r][2]*v2[2];
        float d12 = u2[0]*u1[0] + u2[1]*u1[1] + u2[2]*u1[2];
        u2[0] -= d12 * u1[0]; u2[1] -= d12 * u1[1]; u2[2] -= d12 * u1[2];
        float d2 = u2[0]*u2[0] + u2[1]*u2[1] + u2[2]*u2[2];
        float in2 = (d2 > 1e-30f) ? __frsqrt_rn(d2) : 0.0f;
        u2[0] *= in2; u2[1] *= in2; u2[2] *= in2;

        u3[0] = u1[1]*u2[2] - u1[2]*u2[1];
        u3[1] = u1[2]*u2[0] - u1[0]*u2[2];
        u3[2] = u1[0]*u2[1] - u1[1]*u2[0];

        float R[3][3];
#pragma unroll
        for (int r = 0; r < 3; r++)
#pragma unroll
            for (int c = 0; c < 3; c++)
                R[r][c] = v1[r]*u1[c] + v2[r]*u2[c] + v3[r]*u3[c];

        float det = R[0][0]*(R[1][1]*R[2][2] - R[1][2]*R[2][1])
                  - R[0][1]*(R[1][0]*R[2][2] - R[1][2]*R[2][0])
                  + R[0][2]*(R[1][0]*R[2][1] - R[1][1]*R[2][0]);
        if (det < 0.0f) {
#pragma unroll
            for (int r = 0; r < 3; r++)
#pragma unroll
                for (int c = 0; c < 3; c++)
                    R[r][c] -= 2.0f * v3[r] * u3[c];
        }

        long long ro = (long long)b * 9;
#pragma unroll
        for (int r = 0; r < 3; r++)
#pragma unroll
            for (int c = 0; c < 3; c++)
                outR[ro + r*3 + c] = R[r][c];

        long long to = (long long)b * 3;
#pragma unroll
        for (int c = 0; c < 3; c++) {
            float tc = cB[c] - (R[c][0]*cA[0] + R[c][1]*cA[1] + R[c][2]*cA[2]);
            outT[to + c] = tc;
        }
    }
}

extern "C" void kernel_launch(void* const* d_in, const int* in_sizes, int n_in,
                              void* d_out, int out_size)
{
    const float* pcld = (const float*)d_in[0];  // [b,n,3]
    const float* kpts = (const float*)d_in[1];  // [b,n,8,3]
    const float* cpt  = (const float*)d_in[2];  // [b,n,1,3]
    const float* seg  = (const float*)d_in[3];  // [b,n,1]
    const float* mesh = (const float*)d_in[4];  // [b,9,3]

    int b = in_sizes[4] / 27;       // mesh is b*9*3
    int n = in_sizes[3] / b;        // seg is b*n

    float* out  = (float*)d_out;
    float* outR = out;                      // b*9
    float* outT = out + (long long)b * 9;   // b*3
    float* outV = out + (long long)b * 12;  // b*27

    pose_fused_kernel<<<b, TPB>>>(pcld, kpts, cpt, seg, mesh, outR, outT, outV, n);
}